// round 2
// baseline (speedup 1.0000x reference)
#include <cuda_runtime.h>
#include <cuda_bf16.h>
#include <cstdint>
#include <cstddef>

#define Vv 10000
#define Tt 5
#define Ee 256
#define Hh 512
#define Bb 64
#define Ss 512
#define Gg 2048  /* 4H */

/* ---------------- static device scratch (no allocations) ---------------- */
__device__ float g_P[(size_t)Vv * 4096];                 /* [v][dir*2048+g], bias folded */
__device__ float g_xg[(size_t)2 * Ss * Bb * Gg];         /* [d][s][b][g] */
__device__ float g_hbuf[2 * 2 * Hh * Bb];                /* [d][parity][k][b] */
__device__ float g_lstm[(size_t)Ss * Bb * 2 * Hh];       /* [s][b][2H] */
__device__ float g_em[(size_t)Bb * Ss * Tt];             /* [b][s][t] */
__device__ int   g_xT[Ss * Bb];                          /* [s][b] */
__device__ float g_scores[Bb];
__device__ unsigned g_barc[2];
__device__ volatile unsigned g_barg[2];

/* ------------------------------- prep ----------------------------------- */
__global__ void prep_kernel(const int* __restrict__ x)
{
    int i = blockIdx.x * blockDim.x + threadIdx.x;       /* 512*256 = 131072 */
    if (i < 2 * 2 * Hh * Bb) g_hbuf[i] = 0.f;
    if (i < Ss * Bb) { int s = i >> 6, b = i & 63; g_xT[i] = x[b * Ss + s]; }
    if (i < 2) { g_barc[i] = 0; g_barg[i] = 0; }
}

/* ------------------- vocab projection: P = emb @ Wih^T + b --------------- */
__global__ void __launch_bounds__(256) proj_kernel(
    const float* __restrict__ emb,
    const float* __restrict__ Wf, const float* __restrict__ bf,
    const float* __restrict__ Wb, const float* __restrict__ bb)
{
    __shared__ float sA[32 * 68];
    __shared__ float sB[32 * 68];
    const int v0 = blockIdx.x * 64;
    const int g0 = blockIdx.y * 64;
    const float* W  = (g0 < 2048) ? Wf : Wb;
    const float* bi = (g0 < 2048) ? bf : bb;
    const int gb    = (g0 < 2048) ? g0 : g0 - 2048;
    const int tid = threadIdx.x;
    const int tx = tid & 15, ty = tid >> 4;

    float acc[4][4];
#pragma unroll
    for (int i = 0; i < 4; i++)
#pragma unroll
        for (int j = 0; j < 4; j++) acc[i][j] = 0.f;

    for (int e0 = 0; e0 < Ee; e0 += 32) {
#pragma unroll
        for (int it = 0; it < 2; it++) {
            int lin = tid + it * 256;       /* 0..511 */
            int row = lin >> 3;             /* 0..63  */
            int q   = lin & 7;              /* float4 chunk */
            int v = v0 + row; if (v >= Vv) v = Vv - 1;
            float4 a = *(const float4*)&emb[(size_t)v * Ee + e0 + q * 4];
            sA[(q * 4 + 0) * 68 + row] = a.x;
            sA[(q * 4 + 1) * 68 + row] = a.y;
            sA[(q * 4 + 2) * 68 + row] = a.z;
            sA[(q * 4 + 3) * 68 + row] = a.w;
            float4 w = *(const float4*)&W[(size_t)(gb + row) * Ee + e0 + q * 4];
            sB[(q * 4 + 0) * 68 + row] = w.x;
            sB[(q * 4 + 1) * 68 + row] = w.y;
            sB[(q * 4 + 2) * 68 + row] = w.z;
            sB[(q * 4 + 3) * 68 + row] = w.w;
        }
        __syncthreads();
#pragma unroll
        for (int e = 0; e < 32; e++) {
            float4 a4 = *(const float4*)&sA[e * 68 + tx * 4];
            float4 b4 = *(const float4*)&sB[e * 68 + ty * 4];
            float av[4] = {a4.x, a4.y, a4.z, a4.w};
            float bv[4] = {b4.x, b4.y, b4.z, b4.w};
#pragma unroll
            for (int i = 0; i < 4; i++)
#pragma unroll
                for (int j = 0; j < 4; j++) acc[i][j] += av[i] * bv[j];
        }
        __syncthreads();
    }
#pragma unroll
    for (int i = 0; i < 4; i++) {
        int v = v0 + tx * 4 + i;
        if (v < Vv) {
#pragma unroll
            for (int j = 0; j < 4; j++) {
                int g = gb + ty * 4 + j;
                g_P[(size_t)v * 4096 + g0 + ty * 4 + j] = acc[i][j] + bi[g];
            }
        }
    }
}

/* ------------------ gather: xg[d][s][b][:] = P[x[b][s]][d][:] ------------ */
__global__ void gather_kernel(const int* __restrict__ x)
{
    int sb = blockIdx.x;          /* 0..1023 */
    int s = sb >> 1, d = sb & 1;
    int t = threadIdx.x;          /* 256 */
    for (int b = 0; b < Bb; b++) {
        int tok = x[b * Ss + s];
        const float4* src = (const float4*)(g_P + (size_t)tok * 4096 + d * 2048);
        float4* dst = (float4*)(g_xg + ((size_t)(d * Ss + s) * Bb + b) * Gg);
#pragma unroll
        for (int i = 0; i < 2; i++) dst[t + i * 256] = src[t + i * 256];
    }
}

/* ------------------------- persistent BiLSTM ----------------------------- */
#define LSTM_SMEM ((32 * 513 + Hh * Bb + 32 * Bb) * 4)

__device__ __forceinline__ float sigm(float x) { return 1.f / (1.f + expf(-x)); }

__device__ __forceinline__ void cell_update(
    const float* gate_s, float* hdst, int s, int d, int u0, int u, int b,
    float& c, float& h)
{
    float ig = gate_s[(u)      * Bb + b];
    float fg = gate_s[(8 + u)  * Bb + b];
    float gg = gate_s[(16 + u) * Bb + b];
    float og = gate_s[(24 + u) * Bb + b];
    float cn = sigm(fg) * c + sigm(ig) * tanhf(gg);
    float hn = sigm(og) * tanhf(cn);
    float outv;
    if (g_xT[s * Bb + b] != 0) { c = cn; h = hn; outv = hn; }
    else                       { outv = 0.f; }
    hdst[(u0 + u) * Bb + b] = h;
    g_lstm[((size_t)s * Bb + b) * (2 * Hh) + d * Hh + u0 + u] = outv;
}

__global__ void __launch_bounds__(256, 1) lstm_kernel(
    const float* __restrict__ Whh_f, const float* __restrict__ Whh_b)
{
    extern __shared__ float smem[];
    float* Whh_s  = smem;                    /* [32][513] padded */
    float* h_s    = smem + 32 * 513;         /* [512][64] */
    float* gate_s = h_s + Hh * Bb;           /* [32][64]  */

    const int t   = threadIdx.x;
    const int bid = blockIdx.x;
    const int d   = bid >> 6;
    const int u0  = (bid & 63) * 8;
    const float* Whh = d ? Whh_b : Whh_f;

    /* load this block's 32 Whh rows (i,f,g,o x 8 units), resident all steps */
    for (int i = t; i < 32 * Hh; i += 256) {
        int r = i >> 9, k = i & 511;
        int type = r >> 3, u = r & 7;
        Whh_s[r * 513 + k] = Whh[(size_t)(type * Hh + u0 + u) * Hh + k];
    }

    float c0 = 0.f, c1 = 0.f, h0 = 0.f, h1 = 0.f;   /* cell state in regs */
    const int r  = t >> 3;
    const int b0 = (t & 7) * 8;
    const int grow = (r >> 3) * Hh + u0 + (r & 7);
    const int cu_u = t >> 6;     /* cell-update unit 0..3 (+4 for second) */
    const int cu_b = t & 63;
    __syncthreads();

    for (int step = 0; step < Ss; step++) {
        const int s = d ? (Ss - 1 - step) : step;
        const int p = step & 1;

        /* stage h(prev) from global (L2) into smem */
        const float4* hsrc = (const float4*)(g_hbuf + (size_t)(d * 2 + p) * Hh * Bb);
#pragma unroll
        for (int i = 0; i < (Hh * Bb / 4) / 256; i++)
            ((float4*)h_s)[t + i * 256] = __ldcg(hsrc + t + i * 256);
        __syncthreads();

        /* gates: acc = xg + h @ Whh_slice^T (8 batches per thread) */
        float acc[8];
        {
            const float* xgp = g_xg + ((size_t)(d * Ss + s) * Bb) * Gg + grow;
#pragma unroll
            for (int j = 0; j < 8; j++) acc[j] = __ldg(xgp + (size_t)(b0 + j) * Gg);
        }
        const float* wrow = Whh_s + r * 513;
#pragma unroll 4
        for (int k = 0; k < Hh; k++) {
            float w = wrow[k];
            float4 ha = *(const float4*)&h_s[k * Bb + b0];
            float4 hb = *(const float4*)&h_s[k * Bb + b0 + 4];
            acc[0] += w * ha.x; acc[1] += w * ha.y;
            acc[2] += w * ha.z; acc[3] += w * ha.w;
            acc[4] += w * hb.x; acc[5] += w * hb.y;
            acc[6] += w * hb.z; acc[7] += w * hb.w;
        }
#pragma unroll
        for (int j = 0; j < 8; j++) gate_s[r * Bb + b0 + j] = acc[j];
        __syncthreads();

        /* cell update (2 cells per thread), write h to other parity buffer */
        float* hdst = g_hbuf + (size_t)(d * 2 + (1 - p)) * Hh * Bb;
        cell_update(gate_s, hdst, s, d, u0, cu_u,     cu_b, c0, h0);
        cell_update(gate_s, hdst, s, d, u0, cu_u + 4, cu_b, c1, h1);

        /* inter-block barrier (per direction, epoch counter) */
        __threadfence();
        __syncthreads();
        if (t == 0) {
            unsigned target = 64u * (unsigned)(step + 1);
            unsigned v = atomicAdd(&g_barc[d], 1u);
            if (v == target - 1u) g_barg[d] = target;
            else { while (g_barg[d] < target) { } }
            __threadfence();
        }
        __syncthreads();
    }
}

/* ------------------------- emissions GEMM -------------------------------- */
__global__ void emis_kernel(const float* __restrict__ Wlin,
                            const float* __restrict__ blin)
{
    __shared__ float sW[Tt * 2 * Hh];
    int s = blockIdx.x;
    int t = threadIdx.x;              /* 320 */
    for (int i = t; i < Tt * 2 * Hh; i += 320) sW[i] = Wlin[i];
    __syncthreads();
    int b = t / 5, tag = t % 5;
    const float4* row = (const float4*)(g_lstm + ((size_t)s * Bb + b) * (2 * Hh));
    const float4* w4  = (const float4*)(sW + tag * 2 * Hh);
    float acc = 0.f;
#pragma unroll 4
    for (int k = 0; k < (2 * Hh) / 4; k++) {
        float4 a = __ldg((const float4*)row + k);
        float4 w = w4[k];
        acc += a.x * w.x + a.y * w.y + a.z * w.z + a.w * w.w;
    }
    g_em[((size_t)b * Ss + s) * Tt + tag] = acc + blin[tag];
}

/* ------------------------------ CRF -------------------------------------- */
__global__ void crf_kernel(const int* __restrict__ tags,
                           const int* __restrict__ lengths,
                           const float* __restrict__ trans,
                           const float* __restrict__ start_t,
                           const float* __restrict__ end_t)
{
    int b = blockIdx.x, lane = threadIdx.x;
    const int* tg = tags + (size_t)b * Ss;
    int len = lengths[b];

    /* numerator (lane-parallel over s) */
    float num = 0.f;
    for (int s = lane; s < len; s += 32) {
        int tc = tg[s];
        float e = g_em[((size_t)b * Ss + s) * Tt + tc];
        if (s == 0) num += start_t[tc] + e;
        else        num += trans[tg[s - 1] * Tt + tc] + e;
    }
#pragma unroll
    for (int o = 16; o; o >>= 1) num += __shfl_down_sync(0xffffffffu, num, o);
    num = __shfl_sync(0xffffffffu, num, 0);
    if (lane == 0) num += end_t[tg[len - 1]];
    num = __shfl_sync(0xffffffffu, num, 0);

    /* forward algorithm on lanes 0..4 */
    int lt = lane < 5 ? lane : 0;
    float trc[5];
#pragma unroll
    for (int i = 0; i < 5; i++) trc[i] = trans[i * Tt + lt];
    float alpha = start_t[lt] + g_em[((size_t)b * Ss) * Tt + lt];
    for (int s = 1; s < len; s++) {
        float a[5];
#pragma unroll
        for (int i = 0; i < 5; i++)
            a[i] = __shfl_sync(0xffffffffu, alpha, i) + trc[i];
        float mx = a[0];
#pragma unroll
        for (int i = 1; i < 5; i++) mx = fmaxf(mx, a[i]);
        float ssum = 0.f;
#pragma unroll
        for (int i = 0; i < 5; i++) ssum += expf(a[i] - mx);
        float an = mx + logf(ssum) + g_em[((size_t)b * Ss + s) * Tt + lt];
        if (lane < 5) alpha = an;
    }
    float v = (lane < 5) ? alpha + end_t[lane] : -3.0e38f;
    float mx = v;
#pragma unroll
    for (int o = 16; o; o >>= 1) mx = fmaxf(mx, __shfl_xor_sync(0xffffffffu, mx, o));
    float e = (lane < 5) ? expf(v - mx) : 0.f;
#pragma unroll
    for (int o = 16; o; o >>= 1) e += __shfl_xor_sync(0xffffffffu, e, o);
    if (lane == 0) g_scores[b] = mx + logf(e) - num;
}

/* ------------------------------ mean ------------------------------------- */
__global__ void finish_kernel(float* __restrict__ out)
{
    int t = threadIdx.x;  /* 32 */
    float v = g_scores[t] + g_scores[t + 32];
#pragma unroll
    for (int o = 16; o; o >>= 1) v += __shfl_down_sync(0xffffffffu, v, o);
    if (t == 0) out[0] = v * (1.f / 64.f);
}

/* --------------------------- launcher ------------------------------------ */
extern "C" void kernel_launch(void* const* d_in, const int* in_sizes, int n_in,
                              void* d_out, int out_size)
{
    const int*   x       = (const int*)d_in[0];
    const int*   tags    = (const int*)d_in[1];
    const int*   lengths = (const int*)d_in[2];
    const float* emb     = (const float*)d_in[3];
    const float* Wih_f   = (const float*)d_in[4];
    const float* Whh_f   = (const float*)d_in[5];
    const float* b_f     = (const float*)d_in[6];
    const float* Wih_b   = (const float*)d_in[7];
    const float* Whh_b   = (const float*)d_in[8];
    const float* b_b     = (const float*)d_in[9];
    const float* Wlin    = (const float*)d_in[10];
    const float* blin    = (const float*)d_in[11];
    const float* trans   = (const float*)d_in[12];
    const float* start_t = (const float*)d_in[13];
    const float* end_t   = (const float*)d_in[14];
    float* out = (float*)d_out;

    cudaFuncSetAttribute(lstm_kernel,
                         cudaFuncAttributeMaxDynamicSharedMemorySize, LSTM_SMEM);

    prep_kernel<<<512, 256>>>(x);
    proj_kernel<<<dim3((Vv + 63) / 64, 4096 / 64), 256>>>(emb, Wih_f, b_f, Wih_b, b_b);
    gather_kernel<<<2 * Ss, 256>>>(x);
    lstm_kernel<<<128, 256, LSTM_SMEM>>>(Whh_f, Whh_b);
    emis_kernel<<<Ss, 320>>>(Wlin, blin);
    crf_kernel<<<Bb, 32>>>(tags, lengths, trans, start_t, end_t);
    finish_kernel<<<1, 32>>>(out);
}

// round 4
// speedup vs baseline: 2.5056x; 2.5056x over previous
#include <cuda_runtime.h>
#include <cuda_bf16.h>
#include <cstdint>
#include <cstddef>

#define Vv 10000
#define Tt 5
#define Ee 256
#define Hh 512
#define Bb 64
#define Ss 512
#define Gg 2048  /* 4H */

/* packed f32x2 helpers (sm_100+) */
#define FMA2(acc, x, y) asm("fma.rn.f32x2 %0, %1, %2, %0;" : "+l"(acc) : "l"(x), "l"(y))
#define ADD2(d, x, y)   asm("add.rn.f32x2 %0, %1, %2;" : "=l"(d) : "l"(x), "l"(y))
#define PACK2(d, f)     asm("mov.b64 %0, {%1, %1};" : "=l"(d) : "f"(f))

/* ---------------- static device scratch (no allocations) ---------------- */
__device__ float g_P[(size_t)Vv * 4096];                 /* [v][dir*2048+g], bias folded */
__device__ float g_xg[(size_t)2 * Ss * Bb * Gg];         /* [d][s][b][g] */
__device__ float g_hbuf[2 * 2 * Hh * Bb];                /* [d][parity][k][b] */
__device__ float g_lstm[(size_t)Ss * 2 * Hh * Bb];       /* [s][h2][b] */
__device__ float g_em[(size_t)Bb * Ss * Tt];             /* [b][s][t] */
__device__ int   g_xT[Ss * Bb];                          /* [s][b] */
__device__ float g_scores[Bb];
__device__ unsigned g_barc[2];
__device__ volatile unsigned g_barg[2];

/* ------------------------------- prep ----------------------------------- */
__global__ void prep_kernel(const int* __restrict__ x)
{
    int i = blockIdx.x * blockDim.x + threadIdx.x;       /* 512*256 = 131072 */
    if (i < 2 * 2 * Hh * Bb) g_hbuf[i] = 0.f;
    if (i < Ss * Bb) { int s = i >> 6, b = i & 63; g_xT[i] = x[b * Ss + s]; }
    if (i < 2) { g_barc[i] = 0; g_barg[i] = 0; }
}

/* ------------------- vocab projection: P = emb @ Wih^T + b --------------- */
__global__ void __launch_bounds__(256) proj_kernel(
    const float* __restrict__ emb,
    const float* __restrict__ Wf, const float* __restrict__ bf,
    const float* __restrict__ Wb, const float* __restrict__ bb)
{
    __shared__ float sA[32 * 68];
    __shared__ float sB[32 * 68];
    const int v0 = blockIdx.x * 64;
    const int g0 = blockIdx.y * 64;
    const float* W  = (g0 < 2048) ? Wf : Wb;
    const float* bi = (g0 < 2048) ? bf : bb;
    const int gb    = (g0 < 2048) ? g0 : g0 - 2048;
    const int tid = threadIdx.x;
    const int tx = tid & 15, ty = tid >> 4;

    float acc[4][4];
#pragma unroll
    for (int i = 0; i < 4; i++)
#pragma unroll
        for (int j = 0; j < 4; j++) acc[i][j] = 0.f;

    for (int e0 = 0; e0 < Ee; e0 += 32) {
#pragma unroll
        for (int it = 0; it < 2; it++) {
            int lin = tid + it * 256;
            int row = lin >> 3;
            int q   = lin & 7;
            int v = v0 + row; if (v >= Vv) v = Vv - 1;
            float4 a = *(const float4*)&emb[(size_t)v * Ee + e0 + q * 4];
            sA[(q * 4 + 0) * 68 + row] = a.x;
            sA[(q * 4 + 1) * 68 + row] = a.y;
            sA[(q * 4 + 2) * 68 + row] = a.z;
            sA[(q * 4 + 3) * 68 + row] = a.w;
            float4 w = *(const float4*)&W[(size_t)(gb + row) * Ee + e0 + q * 4];
            sB[(q * 4 + 0) * 68 + row] = w.x;
            sB[(q * 4 + 1) * 68 + row] = w.y;
            sB[(q * 4 + 2) * 68 + row] = w.z;
            sB[(q * 4 + 3) * 68 + row] = w.w;
        }
        __syncthreads();
#pragma unroll
        for (int e = 0; e < 32; e++) {
            float4 a4 = *(const float4*)&sA[e * 68 + tx * 4];
            float4 b4 = *(const float4*)&sB[e * 68 + ty * 4];
            float av[4] = {a4.x, a4.y, a4.z, a4.w};
            float bv[4] = {b4.x, b4.y, b4.z, b4.w};
#pragma unroll
            for (int i = 0; i < 4; i++)
#pragma unroll
                for (int j = 0; j < 4; j++) acc[i][j] += av[i] * bv[j];
        }
        __syncthreads();
    }
#pragma unroll
    for (int i = 0; i < 4; i++) {
        int v = v0 + tx * 4 + i;
        if (v < Vv) {
#pragma unroll
            for (int j = 0; j < 4; j++) {
                int g = gb + ty * 4 + j;
                g_P[(size_t)v * 4096 + g0 + ty * 4 + j] = acc[i][j] + bi[g];
            }
        }
    }
}

/* ------------------ gather: xg[d][s][b][:] = P[x[b][s]][d][:] ------------ */
__global__ void gather_kernel(const int* __restrict__ x)
{
    int sb = blockIdx.x;          /* 0..1023 */
    int s = sb >> 1, d = sb & 1;
    int t = threadIdx.x;          /* 256 */
    for (int b = 0; b < Bb; b++) {
        int tok = x[b * Ss + s];
        const float4* src = (const float4*)(g_P + (size_t)tok * 4096 + d * 2048);
        float4* dst = (float4*)(g_xg + ((size_t)(d * Ss + s) * Bb + b) * Gg);
#pragma unroll
        for (int i = 0; i < 2; i++) dst[t + i * 256] = src[t + i * 256];
    }
}

/* ------------------------- persistent BiLSTM -----------------------------
   Block = 8 hidden units (32 gate rows) x 64 batches of one direction.
   smem: Whh_sT [512][36] transposed weights (73728B)
         h_s    [512][68] staged h, also reduction scratch (139264B)
         gate_s [32][64]  final gates (8192B)                total 221184B
   Threads (256): bg = t&7 (8 batch-grp), kg = (t>>3)&7 (8 k-grp),
                  rg = t>>6 (4 row-grp = gate type).
   Thread tile: 8 rows x 8 batches (as 4 f32x2 pairs) over 64 k. */
#define W_PITCH 36
#define H_PITCH 68
#define LSTM_SMEM ((512 * W_PITCH + 512 * H_PITCH + 32 * 64) * 4)

__device__ __forceinline__ float sigm(float x) { return 1.f / (1.f + expf(-x)); }

__global__ void __launch_bounds__(256, 1) lstm_kernel(
    const float* __restrict__ Whh_f, const float* __restrict__ Whh_b)
{
    extern __shared__ float smem[];
    float* Whh_sT = smem;                       /* [k][36] cols 0..31 = rows */
    float* h_s    = smem + 512 * W_PITCH;       /* [k][68] cols 0..63 = b    */
    float* gate_s = h_s + 512 * H_PITCH;        /* [32][64]                  */
    unsigned long long* sc = (unsigned long long*)h_s;   /* reduction scratch */

    const int t   = threadIdx.x;
    const int bid = blockIdx.x;
    const int d   = bid >> 6;
    const int u0  = (bid & 63) * 8;
    const float* Whh = d ? Whh_b : Whh_f;

    /* load Whh slice transposed: Whh_sT[k][r], r = type*8+u */
    for (int i = t; i < 32 * Hh; i += 256) {
        int r = i >> 9, k = i & 511;
        int type = r >> 3, u = r & 7;
        Whh_sT[k * W_PITCH + r] = Whh[(size_t)(type * Hh + u0 + u) * Hh + k];
    }

    const int bg = t & 7;
    const int kg = (t >> 3) & 7;
    const int rg = t >> 6;
    const int cu_u = t >> 6;      /* cell-update: unit 0..3 (+4) */
    const int cu_b = t & 63;

    float c0 = 0.f, c1 = 0.f, h0 = 0.f, h1 = 0.f;
    __syncthreads();

    for (int step = 0; step < Ss; step++) {
        const int s = d ? (Ss - 1 - step) : step;
        const int p = step & 1;

        /* prefetch xg + mask for cell-update role */
        float xr[8];
        {
            const float* xgp = g_xg + ((size_t)(d * Ss + s) * Bb + cu_b) * Gg + u0;
#pragma unroll
            for (int ty = 0; ty < 4; ty++) {
                xr[ty]     = __ldg(xgp + ty * Hh + cu_u);
                xr[4 + ty] = __ldg(xgp + ty * Hh + cu_u + 4);
            }
        }
        const int msk = g_xT[s * Bb + cu_b];

        /* stage h(prev) from global into smem [k][68] */
        {
            const float4* hsrc = (const float4*)(g_hbuf + (size_t)(d * 2 + p) * Hh * Bb);
#pragma unroll
            for (int i = 0; i < 32; i++) {
                int gi = t + i * 256;            /* float4 index, 0..8191 */
                int k = gi >> 4, c = gi & 15;
                float4 v = __ldcg(hsrc + gi);
                *(float4*)&h_s[k * H_PITCH + c * 4] = v;
            }
        }
        __syncthreads();

        /* GEMM: 8 rows x 8 batches over k in [kg*64, kg*64+64)
           batches: bg*4..bg*4+3 (ha) and 32+bg*4..32+bg*4+3 (hb) */
        unsigned long long a[32];
#pragma unroll
        for (int i = 0; i < 32; i++) a[i] = 0ull;
        {
            const float* wbase = Whh_sT + (size_t)(kg << 6) * W_PITCH + rg * 8;
            const float* hbase = h_s    + (size_t)(kg << 6) * H_PITCH + bg * 4;
#pragma unroll 2
            for (int kk = 0; kk < 64; kk++) {
                const float* hp = hbase + kk * H_PITCH;
                ulonglong2 ha = *(const ulonglong2*)hp;
                ulonglong2 hb = *(const ulonglong2*)(hp + 32);   /* +32 floats */
                const float* wp = wbase + kk * W_PITCH;
                float4 wa = *(const float4*)wp;
                float4 wb = *(const float4*)(wp + 4);
                float ws[8] = {wa.x, wa.y, wa.z, wa.w, wb.x, wb.y, wb.z, wb.w};
#pragma unroll
                for (int i = 0; i < 8; i++) {
                    unsigned long long w2;
                    PACK2(w2, ws[i]);
                    FMA2(a[i * 4 + 0], w2, ha.x);
                    FMA2(a[i * 4 + 1], w2, ha.y);
                    FMA2(a[i * 4 + 2], w2, hb.x);
                    FMA2(a[i * 4 + 3], w2, hb.y);
                }
            }
        }
        __syncthreads();   /* h_s reads done -> reuse as scratch */

        /* tree reduction over kg (bits 5,4,3 of t) */
        if (t & 32) {
#pragma unroll
            for (int i = 0; i < 32; i++) sc[t * 32 + i] = a[i];
        }
        __syncthreads();
        if (!(t & 32)) {
#pragma unroll
            for (int i = 0; i < 32; i++) ADD2(a[i], a[i], sc[(t + 32) * 32 + i]);
        }
        __syncthreads();
        if (!(t & 32) && (t & 16)) {
#pragma unroll
            for (int i = 0; i < 32; i++) sc[t * 32 + i] = a[i];
        }
        __syncthreads();
        if (!(t & 48)) {
#pragma unroll
            for (int i = 0; i < 32; i++) ADD2(a[i], a[i], sc[(t + 16) * 32 + i]);
        }
        __syncthreads();
        if (!(t & 48) && (t & 8)) {
#pragma unroll
            for (int i = 0; i < 32; i++) sc[t * 32 + i] = a[i];
        }
        __syncthreads();
        if (!(t & 56)) {
#pragma unroll
            for (int i = 0; i < 32; i++) ADD2(a[i], a[i], sc[(t + 8) * 32 + i]);
            /* write gates: rows rg*8+i, batch pairs */
            unsigned long long* gd = (unsigned long long*)gate_s;
#pragma unroll
            for (int i = 0; i < 8; i++) {
                int row = rg * 8 + i;
#pragma unroll
                for (int j = 0; j < 2; j++) {
                    gd[row * 32 + bg * 2 + j]      = a[i * 4 + j];
                    gd[row * 32 + 16 + bg * 2 + j] = a[i * 4 + 2 + j];
                }
            }
        }
        __syncthreads();

        /* cell update: 2 cells per thread (units cu_u and cu_u+4) */
        float* hdst = g_hbuf + (size_t)(d * 2 + (1 - p)) * Hh * Bb;
#pragma unroll
        for (int cc = 0; cc < 2; cc++) {
            int u = cu_u + cc * 4;
            float ig = gate_s[(u)      * Bb + cu_b] + xr[cc * 4 + 0];
            float fg = gate_s[(8 + u)  * Bb + cu_b] + xr[cc * 4 + 1];
            float gg = gate_s[(16 + u) * Bb + cu_b] + xr[cc * 4 + 2];
            float og = gate_s[(24 + u) * Bb + cu_b] + xr[cc * 4 + 3];
            float& c = cc ? c1 : c0;
            float& h = cc ? h1 : h0;
            float cn = sigm(fg) * c + sigm(ig) * tanhf(gg);
            float hn = sigm(og) * tanhf(cn);
            float outv;
            if (msk != 0) { c = cn; h = hn; outv = hn; }
            else          { outv = 0.f; }
            hdst[(u0 + u) * Bb + cu_b] = h;
            g_lstm[((size_t)s * 2 * Hh + d * Hh + u0 + u) * Bb + cu_b] = outv;
        }

        /* inter-block barrier (per direction, epoch counter) */
        __threadfence();
        __syncthreads();
        if (t == 0) {
            unsigned target = 64u * (unsigned)(step + 1);
            unsigned v = atomicAdd(&g_barc[d], 1u);
            if (v == target - 1u) g_barg[d] = target;
            else { while (g_barg[d] < target) { } }
            __threadfence();
        }
        __syncthreads();
    }
}

/* ------------------------- emissions GEMM --------------------------------
   lstm layout [s][h2][b]: block per s, thread (tag=t>>6, b=t&63), 320 thr. */
__global__ void emis_kernel(const float* __restrict__ Wlin,
                            const float* __restrict__ blin)
{
    __shared__ float sW[Tt * 2 * Hh];
    int s = blockIdx.x;
    int t = threadIdx.x;              /* 320 */
    for (int i = t; i < Tt * 2 * Hh; i += 320) sW[i] = Wlin[i];
    __syncthreads();
    int tag = t >> 6, b = t & 63;
    const float* lp = g_lstm + (size_t)s * 2 * Hh * Bb + b;
    const float* wp = sW + tag * 2 * Hh;
    float acc = 0.f;
#pragma unroll 8
    for (int h = 0; h < 2 * Hh; h++) acc += __ldg(lp + (size_t)h * Bb) * wp[h];
    g_em[((size_t)b * Ss + s) * Tt + tag] = acc + blin[tag];
}

/* ------------------------------ CRF -------------------------------------- */
__global__ void crf_kernel(const int* __restrict__ tags,
                           const int* __restrict__ lengths,
                           const float* __restrict__ trans,
                           const float* __restrict__ start_t,
                           const float* __restrict__ end_t)
{
    int b = blockIdx.x, lane = threadIdx.x;
    const int* tg = tags + (size_t)b * Ss;
    int len = lengths[b];

    float num = 0.f;
    for (int s = lane; s < len; s += 32) {
        int tc = tg[s];
        float e = g_em[((size_t)b * Ss + s) * Tt + tc];
        if (s == 0) num += start_t[tc] + e;
        else        num += trans[tg[s - 1] * Tt + tc] + e;
    }
#pragma unroll
    for (int o = 16; o; o >>= 1) num += __shfl_down_sync(0xffffffffu, num, o);
    num = __shfl_sync(0xffffffffu, num, 0);
    if (lane == 0) num += end_t[tg[len - 1]];
    num = __shfl_sync(0xffffffffu, num, 0);

    int lt = lane < 5 ? lane : 0;
    float trc[5];
#pragma unroll
    for (int i = 0; i < 5; i++) trc[i] = trans[i * Tt + lt];
    float alpha = start_t[lt] + g_em[((size_t)b * Ss) * Tt + lt];
    for (int s = 1; s < len; s++) {
        float av[5];
#pragma unroll
        for (int i = 0; i < 5; i++)
            av[i] = __shfl_sync(0xffffffffu, alpha, i) + trc[i];
        float mx = av[0];
#pragma unroll
        for (int i = 1; i < 5; i++) mx = fmaxf(mx, av[i]);
        float ssum = 0.f;
#pragma unroll
        for (int i = 0; i < 5; i++) ssum += expf(av[i] - mx);
        float an = mx + logf(ssum) + g_em[((size_t)b * Ss + s) * Tt + lt];
        if (lane < 5) alpha = an;
    }
    float v = (lane < 5) ? alpha + end_t[lane] : -3.0e38f;
    float mx = v;
#pragma unroll
    for (int o = 16; o; o >>= 1) mx = fmaxf(mx, __shfl_xor_sync(0xffffffffu, mx, o));
    float e = (lane < 5) ? expf(v - mx) : 0.f;
#pragma unroll
    for (int o = 16; o; o >>= 1) e += __shfl_xor_sync(0xffffffffu, e, o);
    if (lane == 0) g_scores[b] = mx + logf(e) - num;
}

/* ------------------------------ mean ------------------------------------- */
__global__ void finish_kernel(float* __restrict__ out)
{
    int t = threadIdx.x;  /* 32 */
    float v = g_scores[t] + g_scores[t + 32];
#pragma unroll
    for (int o = 16; o; o >>= 1) v += __shfl_down_sync(0xffffffffu, v, o);
    if (t == 0) out[0] = v * (1.f / 64.f);
}

/* --------------------------- launcher ------------------------------------ */
extern "C" void kernel_launch(void* const* d_in, const int* in_sizes, int n_in,
                              void* d_out, int out_size)
{
    const int*   x       = (const int*)d_in[0];
    const int*   tags    = (const int*)d_in[1];
    const int*   lengths = (const int*)d_in[2];
    const float* emb     = (const float*)d_in[3];
    const float* Wih_f   = (const float*)d_in[4];
    const float* Whh_f   = (const float*)d_in[5];
    const float* b_f     = (const float*)d_in[6];
    const float* Wih_b   = (const float*)d_in[7];
    const float* Whh_b   = (const float*)d_in[8];
    const float* b_b     = (const float*)d_in[9];
    const float* Wlin    = (const float*)d_in[10];
    const float* blin    = (const float*)d_in[11];
    const float* trans   = (const float*)d_in[12];
    const float* start_t = (const float*)d_in[13];
    const float* end_t   = (const float*)d_in[14];
    float* out = (float*)d_out;

    cudaFuncSetAttribute(lstm_kernel,
                         cudaFuncAttributeMaxDynamicSharedMemorySize, LSTM_SMEM);

    prep_kernel<<<512, 256>>>(x);
    proj_kernel<<<dim3((Vv + 63) / 64, 4096 / 64), 256>>>(emb, Wih_f, b_f, Wih_b, b_b);
    gather_kernel<<<2 * Ss, 256>>>(x);
    lstm_kernel<<<128, 256, LSTM_SMEM>>>(Whh_f, Whh_b);
    emis_kernel<<<Ss, 320>>>(Wlin, blin);
    crf_kernel<<<Bb, 32>>>(tags, lengths, trans, start_t, end_t);
    finish_kernel<<<1, 32>>>(out);
}

// round 5
// speedup vs baseline: 2.5147x; 1.0037x over previous
#include <cuda_runtime.h>
#include <cuda_bf16.h>
#include <cstdint>
#include <cstddef>

#define Vv 10000
#define Tt 5
#define Ee 256
#define Hh 512
#define Bb 64
#define Ss 512
#define Gg 2048  /* 4H */

/* packed f32x2 helpers (sm_100+) */
#define FMA2(acc, x, y) asm("fma.rn.f32x2 %0, %1, %2, %0;" : "+l"(acc) : "l"(x), "l"(y))
#define ADD2(d, x, y)   asm("add.rn.f32x2 %0, %1, %2;" : "=l"(d) : "l"(x), "l"(y))
#define PACK2(d, f)     asm("mov.b64 %0, {%1, %1};" : "=l"(d) : "f"(f))

/* ---------------- static device scratch (no allocations) ---------------- */
__device__ float g_P[(size_t)Vv * 4096];                 /* [v][dir*2048+g], bias folded */
__device__ float g_xg[(size_t)2 * Ss * Bb * Gg];         /* [d][s][b][g] */
__device__ float g_hbuf[2 * 2 * Hh * Bb];                /* [d][parity][k][b] */
__device__ float g_lstm[(size_t)Ss * 2 * Hh * Bb];       /* [s][h2][b] */
__device__ float g_em[(size_t)Bb * Ss * Tt];             /* [b][s][t] */
__device__ int   g_xT[Ss * Bb];                          /* [s][b] */
__device__ float g_scores[Bb];
__device__ unsigned g_barc[2];
__device__ volatile unsigned g_barg[2];

/* ------------------------------- prep ----------------------------------- */
__global__ void prep_kernel(const int* __restrict__ x)
{
    int i = blockIdx.x * blockDim.x + threadIdx.x;       /* 512*256 = 131072 */
    if (i < 2 * 2 * Hh * Bb) g_hbuf[i] = 0.f;
    if (i < Ss * Bb) { int s = i >> 6, b = i & 63; g_xT[i] = x[b * Ss + s]; }
    if (i < 2) { g_barc[i] = 0; g_barg[i] = 0; }
}

/* ------------------- vocab projection: P = emb @ Wih^T + b --------------- */
__global__ void __launch_bounds__(256) proj_kernel(
    const float* __restrict__ emb,
    const float* __restrict__ Wf, const float* __restrict__ bf,
    const float* __restrict__ Wb, const float* __restrict__ bb)
{
    __shared__ float sA[32 * 68];
    __shared__ float sB[32 * 68];
    const int v0 = blockIdx.x * 64;
    const int g0 = blockIdx.y * 64;
    const float* W  = (g0 < 2048) ? Wf : Wb;
    const float* bi = (g0 < 2048) ? bf : bb;
    const int gb    = (g0 < 2048) ? g0 : g0 - 2048;
    const int tid = threadIdx.x;
    const int tx = tid & 15, ty = tid >> 4;

    float acc[4][4];
#pragma unroll
    for (int i = 0; i < 4; i++)
#pragma unroll
        for (int j = 0; j < 4; j++) acc[i][j] = 0.f;

    for (int e0 = 0; e0 < Ee; e0 += 32) {
#pragma unroll
        for (int it = 0; it < 2; it++) {
            int lin = tid + it * 256;
            int row = lin >> 3;
            int q   = lin & 7;
            int v = v0 + row; if (v >= Vv) v = Vv - 1;
            float4 a = *(const float4*)&emb[(size_t)v * Ee + e0 + q * 4];
            sA[(q * 4 + 0) * 68 + row] = a.x;
            sA[(q * 4 + 1) * 68 + row] = a.y;
            sA[(q * 4 + 2) * 68 + row] = a.z;
            sA[(q * 4 + 3) * 68 + row] = a.w;
            float4 w = *(const float4*)&W[(size_t)(gb + row) * Ee + e0 + q * 4];
            sB[(q * 4 + 0) * 68 + row] = w.x;
            sB[(q * 4 + 1) * 68 + row] = w.y;
            sB[(q * 4 + 2) * 68 + row] = w.z;
            sB[(q * 4 + 3) * 68 + row] = w.w;
        }
        __syncthreads();
#pragma unroll
        for (int e = 0; e < 32; e++) {
            float4 a4 = *(const float4*)&sA[e * 68 + tx * 4];
            float4 b4 = *(const float4*)&sB[e * 68 + ty * 4];
            float av[4] = {a4.x, a4.y, a4.z, a4.w};
            float bv[4] = {b4.x, b4.y, b4.z, b4.w};
#pragma unroll
            for (int i = 0; i < 4; i++)
#pragma unroll
                for (int j = 0; j < 4; j++) acc[i][j] += av[i] * bv[j];
        }
        __syncthreads();
    }
#pragma unroll
    for (int i = 0; i < 4; i++) {
        int v = v0 + tx * 4 + i;
        if (v < Vv) {
#pragma unroll
            for (int j = 0; j < 4; j++) {
                int g = gb + ty * 4 + j;
                g_P[(size_t)v * 4096 + g0 + ty * 4 + j] = acc[i][j] + bi[g];
            }
        }
    }
}

/* ------------------ gather: xg[d][s][b][:] = P[x[b][s]][d][:] ------------ */
__global__ void gather_kernel(const int* __restrict__ x)
{
    int sb = blockIdx.x;          /* 0..1023 */
    int s = sb >> 1, d = sb & 1;
    int t = threadIdx.x;          /* 256 */
    for (int b = 0; b < Bb; b++) {
        int tok = x[b * Ss + s];
        const float4* src = (const float4*)(g_P + (size_t)tok * 4096 + d * 2048);
        float4* dst = (float4*)(g_xg + ((size_t)(d * Ss + s) * Bb + b) * Gg);
#pragma unroll
        for (int i = 0; i < 2; i++) dst[t + i * 256] = src[t + i * 256];
    }
}

/* ------------------------- persistent BiLSTM -----------------------------
   Block = 8 hidden units (32 gate rows) x 64 batches of one direction.
   smem: Whh_sT [512][36] transposed weights (73728B)
         h_s    [512][68] staged h, also reduction scratch (139264B)
         gate_s [32][64]  final gates (8192B)                total 221184B
   Threads (256): bg = t&7 (8 batch-grp), kg = (t>>3)&7 (8 k-grp),
                  rg = t>>6 (4 row-grp = gate type).
   Thread tile: 8 rows x 8 batches (as 4 f32x2 pairs) over 64 k. */
#define W_PITCH 36
#define H_PITCH 68
#define LSTM_SMEM ((512 * W_PITCH + 512 * H_PITCH + 32 * 64) * 4)

__device__ __forceinline__ float sigm(float x) { return 1.f / (1.f + expf(-x)); }

__global__ void __launch_bounds__(256, 1) lstm_kernel(
    const float* __restrict__ Whh_f, const float* __restrict__ Whh_b)
{
    extern __shared__ float smem[];
    float* Whh_sT = smem;                       /* [k][36] cols 0..31 = rows */
    float* h_s    = smem + 512 * W_PITCH;       /* [k][68] cols 0..63 = b    */
    float* gate_s = h_s + 512 * H_PITCH;        /* [32][64]                  */
    unsigned long long* sc = (unsigned long long*)h_s;   /* reduction scratch */

    const int t   = threadIdx.x;
    const int bid = blockIdx.x;
    const int d   = bid >> 6;
    const int u0  = (bid & 63) * 8;
    const float* Whh = d ? Whh_b : Whh_f;

    /* load Whh slice transposed: Whh_sT[k][r], r = type*8+u */
    for (int i = t; i < 32 * Hh; i += 256) {
        int r = i >> 9, k = i & 511;
        int type = r >> 3, u = r & 7;
        Whh_sT[k * W_PITCH + r] = Whh[(size_t)(type * Hh + u0 + u) * Hh + k];
    }

    const int bg = t & 7;
    const int kg = (t >> 3) & 7;
    const int rg = t >> 6;
    const int cu_u = t >> 6;      /* cell-update: unit 0..3 (+4) */
    const int cu_b = t & 63;

    float c0 = 0.f, c1 = 0.f, h0 = 0.f, h1 = 0.f;
    __syncthreads();

    for (int step = 0; step < Ss; step++) {
        const int s = d ? (Ss - 1 - step) : step;
        const int p = step & 1;

        /* prefetch xg + mask for cell-update role */
        float xr[8];
        {
            const float* xgp = g_xg + ((size_t)(d * Ss + s) * Bb + cu_b) * Gg + u0;
#pragma unroll
            for (int ty = 0; ty < 4; ty++) {
                xr[ty]     = __ldg(xgp + ty * Hh + cu_u);
                xr[4 + ty] = __ldg(xgp + ty * Hh + cu_u + 4);
            }
        }
        const int msk = g_xT[s * Bb + cu_b];

        /* stage h(prev) from global into smem [k][68] */
        {
            const float4* hsrc = (const float4*)(g_hbuf + (size_t)(d * 2 + p) * Hh * Bb);
#pragma unroll
            for (int i = 0; i < 32; i++) {
                int gi = t + i * 256;            /* float4 index, 0..8191 */
                int k = gi >> 4, c = gi & 15;
                float4 v = __ldcg(hsrc + gi);
                *(float4*)&h_s[k * H_PITCH + c * 4] = v;
            }
        }
        __syncthreads();

        /* GEMM: 8 rows x 8 batches over k in [kg*64, kg*64+64)
           batches: bg*4..bg*4+3 (ha) and 32+bg*4..32+bg*4+3 (hb) */
        unsigned long long a[32];
#pragma unroll
        for (int i = 0; i < 32; i++) a[i] = 0ull;
        {
            const float* wbase = Whh_sT + (size_t)(kg << 6) * W_PITCH + rg * 8;
            const float* hbase = h_s    + (size_t)(kg << 6) * H_PITCH + bg * 4;
#pragma unroll 2
            for (int kk = 0; kk < 64; kk++) {
                const float* hp = hbase + kk * H_PITCH;
                ulonglong2 ha = *(const ulonglong2*)hp;
                ulonglong2 hb = *(const ulonglong2*)(hp + 32);   /* +32 floats */
                const float* wp = wbase + kk * W_PITCH;
                float4 wa = *(const float4*)wp;
                float4 wb = *(const float4*)(wp + 4);
                float ws[8] = {wa.x, wa.y, wa.z, wa.w, wb.x, wb.y, wb.z, wb.w};
#pragma unroll
                for (int i = 0; i < 8; i++) {
                    unsigned long long w2;
                    PACK2(w2, ws[i]);
                    FMA2(a[i * 4 + 0], w2, ha.x);
                    FMA2(a[i * 4 + 1], w2, ha.y);
                    FMA2(a[i * 4 + 2], w2, hb.x);
                    FMA2(a[i * 4 + 3], w2, hb.y);
                }
            }
        }
        __syncthreads();   /* h_s reads done -> reuse as scratch */

        /* tree reduction over kg (bits 5,4,3 of t) */
        if (t & 32) {
#pragma unroll
            for (int i = 0; i < 32; i++) sc[t * 32 + i] = a[i];
        }
        __syncthreads();
        if (!(t & 32)) {
#pragma unroll
            for (int i = 0; i < 32; i++) ADD2(a[i], a[i], sc[(t + 32) * 32 + i]);
        }
        __syncthreads();
        if (!(t & 32) && (t & 16)) {
#pragma unroll
            for (int i = 0; i < 32; i++) sc[t * 32 + i] = a[i];
        }
        __syncthreads();
        if (!(t & 48)) {
#pragma unroll
            for (int i = 0; i < 32; i++) ADD2(a[i], a[i], sc[(t + 16) * 32 + i]);
        }
        __syncthreads();
        if (!(t & 48) && (t & 8)) {
#pragma unroll
            for (int i = 0; i < 32; i++) sc[t * 32 + i] = a[i];
        }
        __syncthreads();
        if (!(t & 56)) {
#pragma unroll
            for (int i = 0; i < 32; i++) ADD2(a[i], a[i], sc[(t + 8) * 32 + i]);
            /* write gates: rows rg*8+i, batch pairs */
            unsigned long long* gd = (unsigned long long*)gate_s;
#pragma unroll
            for (int i = 0; i < 8; i++) {
                int row = rg * 8 + i;
#pragma unroll
                for (int j = 0; j < 2; j++) {
                    gd[row * 32 + bg * 2 + j]      = a[i * 4 + j];
                    gd[row * 32 + 16 + bg * 2 + j] = a[i * 4 + 2 + j];
                }
            }
        }
        __syncthreads();

        /* cell update: 2 cells per thread (units cu_u and cu_u+4) */
        float* hdst = g_hbuf + (size_t)(d * 2 + (1 - p)) * Hh * Bb;
#pragma unroll
        for (int cc = 0; cc < 2; cc++) {
            int u = cu_u + cc * 4;
            float ig = gate_s[(u)      * Bb + cu_b] + xr[cc * 4 + 0];
            float fg = gate_s[(8 + u)  * Bb + cu_b] + xr[cc * 4 + 1];
            float gg = gate_s[(16 + u) * Bb + cu_b] + xr[cc * 4 + 2];
            float og = gate_s[(24 + u) * Bb + cu_b] + xr[cc * 4 + 3];
            float& c = cc ? c1 : c0;
            float& h = cc ? h1 : h0;
            float cn = sigm(fg) * c + sigm(ig) * tanhf(gg);
            float hn = sigm(og) * tanhf(cn);
            float outv;
            if (msk != 0) { c = cn; h = hn; outv = hn; }
            else          { outv = 0.f; }
            hdst[(u0 + u) * Bb + cu_b] = h;
            g_lstm[((size_t)s * 2 * Hh + d * Hh + u0 + u) * Bb + cu_b] = outv;
        }

        /* inter-block barrier (per direction, epoch counter) */
        __threadfence();
        __syncthreads();
        if (t == 0) {
            unsigned target = 64u * (unsigned)(step + 1);
            unsigned v = atomicAdd(&g_barc[d], 1u);
            if (v == target - 1u) g_barg[d] = target;
            else { while (g_barg[d] < target) { } }
            __threadfence();
        }
        __syncthreads();
    }
}

/* ------------------------- emissions GEMM --------------------------------
   lstm layout [s][h2][b]: block per s, thread (tag=t>>6, b=t&63), 320 thr. */
__global__ void emis_kernel(const float* __restrict__ Wlin,
                            const float* __restrict__ blin)
{
    __shared__ float sW[Tt * 2 * Hh];
    int s = blockIdx.x;
    int t = threadIdx.x;              /* 320 */
    for (int i = t; i < Tt * 2 * Hh; i += 320) sW[i] = Wlin[i];
    __syncthreads();
    int tag = t >> 6, b = t & 63;
    const float* lp = g_lstm + (size_t)s * 2 * Hh * Bb + b;
    const float* wp = sW + tag * 2 * Hh;
    float acc = 0.f;
#pragma unroll 8
    for (int h = 0; h < 2 * Hh; h++) acc += __ldg(lp + (size_t)h * Bb) * wp[h];
    g_em[((size_t)b * Ss + s) * Tt + tag] = acc + blin[tag];
}

/* ------------------------------ CRF -------------------------------------- */
__global__ void crf_kernel(const int* __restrict__ tags,
                           const int* __restrict__ lengths,
                           const float* __restrict__ trans,
                           const float* __restrict__ start_t,
                           const float* __restrict__ end_t)
{
    int b = blockIdx.x, lane = threadIdx.x;
    const int* tg = tags + (size_t)b * Ss;
    int len = lengths[b];

    float num = 0.f;
    for (int s = lane; s < len; s += 32) {
        int tc = tg[s];
        float e = g_em[((size_t)b * Ss + s) * Tt + tc];
        if (s == 0) num += start_t[tc] + e;
        else        num += trans[tg[s - 1] * Tt + tc] + e;
    }
#pragma unroll
    for (int o = 16; o; o >>= 1) num += __shfl_down_sync(0xffffffffu, num, o);
    num = __shfl_sync(0xffffffffu, num, 0);
    if (lane == 0) num += end_t[tg[len - 1]];
    num = __shfl_sync(0xffffffffu, num, 0);

    int lt = lane < 5 ? lane : 0;
    float trc[5];
#pragma unroll
    for (int i = 0; i < 5; i++) trc[i] = trans[i * Tt + lt];
    float alpha = start_t[lt] + g_em[((size_t)b * Ss) * Tt + lt];
    for (int s = 1; s < len; s++) {
        float av[5];
#pragma unroll
        for (int i = 0; i < 5; i++)
            av[i] = __shfl_sync(0xffffffffu, alpha, i) + trc[i];
        float mx = av[0];
#pragma unroll
        for (int i = 1; i < 5; i++) mx = fmaxf(mx, av[i]);
        float ssum = 0.f;
#pragma unroll
        for (int i = 0; i < 5; i++) ssum += expf(av[i] - mx);
        float an = mx + logf(ssum) + g_em[((size_t)b * Ss + s) * Tt + lt];
        if (lane < 5) alpha = an;
    }
    float v = (lane < 5) ? alpha + end_t[lane] : -3.0e38f;
    float mx = v;
#pragma unroll
    for (int o = 16; o; o >>= 1) mx = fmaxf(mx, __shfl_xor_sync(0xffffffffu, mx, o));
    float e = (lane < 5) ? expf(v - mx) : 0.f;
#pragma unroll
    for (int o = 16; o; o >>= 1) e += __shfl_xor_sync(0xffffffffu, e, o);
    if (lane == 0) g_scores[b] = mx + logf(e) - num;
}

/* ------------------------------ mean ------------------------------------- */
__global__ void finish_kernel(float* __restrict__ out)
{
    int t = threadIdx.x;  /* 32 */
    float v = g_scores[t] + g_scores[t + 32];
#pragma unroll
    for (int o = 16; o; o >>= 1) v += __shfl_down_sync(0xffffffffu, v, o);
    if (t == 0) out[0] = v * (1.f / 64.f);
}

/* --------------------------- launcher ------------------------------------ */
extern "C" void kernel_launch(void* const* d_in, const int* in_sizes, int n_in,
                              void* d_out, int out_size)
{
    const int*   x       = (const int*)d_in[0];
    const int*   tags    = (const int*)d_in[1];
    const int*   lengths = (const int*)d_in[2];
    const float* emb     = (const float*)d_in[3];
    const float* Wih_f   = (const float*)d_in[4];
    const float* Whh_f   = (const float*)d_in[5];
    const float* b_f     = (const float*)d_in[6];
    const float* Wih_b   = (const float*)d_in[7];
    const float* Whh_b   = (const float*)d_in[8];
    const float* b_b     = (const float*)d_in[9];
    const float* Wlin    = (const float*)d_in[10];
    const float* blin    = (const float*)d_in[11];
    const float* trans   = (const float*)d_in[12];
    const float* start_t = (const float*)d_in[13];
    const float* end_t   = (const float*)d_in[14];
    float* out = (float*)d_out;

    cudaFuncSetAttribute(lstm_kernel,
                         cudaFuncAttributeMaxDynamicSharedMemorySize, LSTM_SMEM);

    prep_kernel<<<512, 256>>>(x);
    proj_kernel<<<dim3((Vv + 63) / 64, 4096 / 64), 256>>>(emb, Wih_f, b_f, Wih_b, b_b);
    gather_kernel<<<2 * Ss, 256>>>(x);
    lstm_kernel<<<128, 256, LSTM_SMEM>>>(Whh_f, Whh_b);
    emis_kernel<<<Ss, 320>>>(Wlin, blin);
    crf_kernel<<<Bb, 32>>>(tags, lengths, trans, start_t, end_t);
    finish_kernel<<<1, 32>>>(out);
}

// round 7
// speedup vs baseline: 4.1831x; 1.6634x over previous
#include <cuda_runtime.h>
#include <cuda_fp16.h>
#include <cstdint>
#include <cstddef>

#define Vv 10000
#define Tt 5
#define Ee 256
#define Hh 512
#define Bb 64
#define Ss 512
#define Gg 2048

__device__ float g_P[(size_t)Vv * 4096];
__device__ float g_xg[(size_t)2 * Ss * Gg * Bb];          /* [d][s][g][b] */
__device__ __half g_H16[2 * 2 * 2 * 32768];               /* [d][par][hi/lo][k*64+b swizzled] */
__device__ float g_lstm[(size_t)Ss * 2 * Hh * Bb];        /* [s][h2][b] */
__device__ float g_em[(size_t)Bb * Ss * Tt];
__device__ int   g_xT[Ss * Bb];
__device__ float g_scores[Bb];
__device__ unsigned g_barc[2];
__device__ volatile unsigned g_barg[2];

__device__ __forceinline__ uint32_t smem_u32(const void* p) {
    uint32_t a;
    asm("{ .reg .u64 t; cvta.to.shared.u64 t, %1; cvt.u32.u64 %0, t; }" : "=r"(a) : "l"(p));
    return a;
}
#define LDSM4(r0,r1,r2,r3,ad) asm volatile( \
    "ldmatrix.sync.aligned.m8n8.x4.shared.b16 {%0,%1,%2,%3}, [%4];" \
    : "=r"(r0),"=r"(r1),"=r"(r2),"=r"(r3) : "r"(ad))
#define LDSM4T(r0,r1,r2,r3,ad) asm volatile( \
    "ldmatrix.sync.aligned.m8n8.x4.trans.shared.b16 {%0,%1,%2,%3}, [%4];" \
    : "=r"(r0),"=r"(r1),"=r"(r2),"=r"(r3) : "r"(ad))
#define MMA16(d,a0,a1,a2,a3,b0,b1) asm volatile( \
    "mma.sync.aligned.m16n8k16.row.col.f32.f16.f16.f32 " \
    "{%0,%1,%2,%3}, {%4,%5,%6,%7}, {%8,%9}, {%0,%1,%2,%3};" \
    : "+f"((d)[0]),"+f"((d)[1]),"+f"((d)[2]),"+f"((d)[3]) \
    : "r"(a0),"r"(a1),"r"(a2),"r"(a3),"r"(b0),"r"(b1))

/* ---- prep ---- */
__global__ void prep_kernel(const int* __restrict__ x)
{
    int i = blockIdx.x * blockDim.x + threadIdx.x;       /* 131072 */
    ((unsigned*)g_H16)[i] = 0;
    if (i < Ss * Bb) { int s = i >> 6, b = i & 63; g_xT[i] = x[b * Ss + s]; }
    if (i < 2) { g_barc[i] = 0; g_barg[i] = 0; }
}

/* ---- vocab projection: P = emb @ Wih^T + b ---- */
__global__ void __launch_bounds__(256) proj_kernel(
    const float* __restrict__ emb,
    const float* __restrict__ Wf, const float* __restrict__ bf,
    const float* __restrict__ Wb, const float* __restrict__ bb)
{
    __shared__ float sA[32 * 68], sB[32 * 68];
    const int v0 = blockIdx.x * 64, g0 = blockIdx.y * 64;
    const float* W  = (g0 < 2048) ? Wf : Wb;
    const float* bi = (g0 < 2048) ? bf : bb;
    const int gb = (g0 < 2048) ? g0 : g0 - 2048;
    const int tid = threadIdx.x, tx = tid & 15, ty = tid >> 4;
    float acc[4][4];
#pragma unroll
    for (int i = 0; i < 4; i++)
#pragma unroll
        for (int j = 0; j < 4; j++) acc[i][j] = 0.f;
    for (int e0 = 0; e0 < Ee; e0 += 32) {
#pragma unroll
        for (int it = 0; it < 2; it++) {
            int lin = tid + it * 256, row = lin >> 3, q = lin & 7;
            int v = v0 + row; if (v >= Vv) v = Vv - 1;
            float4 a = *(const float4*)&emb[(size_t)v * Ee + e0 + q * 4];
            sA[(q*4+0)*68+row]=a.x; sA[(q*4+1)*68+row]=a.y; sA[(q*4+2)*68+row]=a.z; sA[(q*4+3)*68+row]=a.w;
            float4 w = *(const float4*)&W[(size_t)(gb + row) * Ee + e0 + q * 4];
            sB[(q*4+0)*68+row]=w.x; sB[(q*4+1)*68+row]=w.y; sB[(q*4+2)*68+row]=w.z; sB[(q*4+3)*68+row]=w.w;
        }
        __syncthreads();
#pragma unroll
        for (int e = 0; e < 32; e++) {
            float4 a4 = *(const float4*)&sA[e * 68 + tx * 4];
            float4 b4 = *(const float4*)&sB[e * 68 + ty * 4];
            float av[4] = {a4.x, a4.y, a4.z, a4.w}, bv[4] = {b4.x, b4.y, b4.z, b4.w};
#pragma unroll
            for (int i = 0; i < 4; i++)
#pragma unroll
                for (int j = 0; j < 4; j++) acc[i][j] += av[i] * bv[j];
        }
        __syncthreads();
    }
#pragma unroll
    for (int i = 0; i < 4; i++) {
        int v = v0 + tx * 4 + i;
        if (v < Vv)
#pragma unroll
            for (int j = 0; j < 4; j++)
                g_P[(size_t)v * 4096 + g0 + ty * 4 + j] = acc[i][j] + bi[gb + ty * 4 + j];
    }
}

/* ---- gather+transpose: xg[d][s][g][b] = P[x[b][s]][d*2048+g] ---- */
__global__ void gather_kernel(const int* __restrict__ x)
{
    __shared__ float tile[64 * 68];
    int sb = blockIdx.x, s = sb >> 1, d = sb & 1, t = threadIdx.x;
    int lb = t & 63, lq = t >> 6, wg = t >> 2, wq = t & 3;
    int tok = x[lb * Ss + s];
    const float* src = g_P + (size_t)tok * 4096 + d * 2048;
    float* dst = g_xg + ((size_t)(d * Ss + s)) * Gg * Bb;
    for (int g0 = 0; g0 < Gg; g0 += 64) {
#pragma unroll
        for (int j = 0; j < 4; j++) {
            int col = lq * 16 + j * 4;
            *(float4*)&tile[lb * 68 + col] = __ldg((const float4*)&src[g0 + col]);
        }
        __syncthreads();
        float o[16];
#pragma unroll
        for (int i = 0; i < 16; i++) o[i] = tile[(wq * 16 + i) * 68 + wg];
        float4* ob = (float4*)&dst[(size_t)(g0 + wg) * Bb + wq * 16];
#pragma unroll
        for (int i = 0; i < 4; i++) ob[i] = ((float4*)o)[i];
        __syncthreads();
    }
}

/* ---- persistent BiLSTM via mma.sync f16 (3-term split) ----
   128 blocks: d(2) x m(64). Block: 8 hidden units = 32 gate rows x 64 b,
   K = 512. Warp (8): wm = wid&1 (m16), wn = wid>>1 (n16), full K.
   smem: A_hi 32KB, A_lo 32KB (resident, swizzled [m][k] rows 1KB),
         B_hi 64KB, B_lo 64KB (staged per step, swizzled [k][b] rows 128B),
         gates [32][66] f32. */
#define OFF_AH 0
#define OFF_AL 32768
#define OFF_BH 65536
#define OFF_BL 131072
#define OFF_G  196608
#define GP 66
#define LSTM_SMEM (OFF_G + 32 * GP * 4)

__device__ __forceinline__ float sigm(float x) { return 1.f / (1.f + expf(-x)); }

__global__ void __launch_bounds__(256, 1) lstm_kernel(
    const float* __restrict__ Whh_f, const float* __restrict__ Whh_b)
{
    extern __shared__ char smem[];
    const uint32_t sb = smem_u32(smem);
    float* gate_s = (float*)(smem + OFF_G);
    const int t = threadIdx.x, lane = t & 31, wid = t >> 5;
    const int d = blockIdx.x >> 6, mblk = blockIdx.x & 63;
    const int u0 = mblk * 8;
    const float* Whh = d ? Whh_b : Whh_f;

    /* A split hi/lo into swizzled smem: row r = type*8+u, 1KB rows */
    for (int i = t; i < 32 * 512; i += 256) {
        int r = i >> 9, k = i & 511;
        float w = Whh[(size_t)((r >> 3) * Hh + u0 + (r & 7)) * Hh + k];
        __half hi = __float2half_rn(w);
        __half lo = __float2half_rn(w - __half2float(hi));
        uint32_t off = (uint32_t)r * 1024 + ((((k >> 3) ^ (r & 7))) << 4) + (k & 7) * 2;
        *(__half*)(smem + OFF_AH + off) = hi;
        *(__half*)(smem + OFF_AL + off) = lo;
    }

    /* GEMM role constants */
    const int wm = wid & 1, wn = wid >> 1;
    const int m_l = wm * 16 + (lane & 15);
    const int kh  = lane >> 4;
    const int me7 = m_l & 7;
    const uint32_t aBH = sb + OFF_AH + m_l * 1024;
    const uint32_t aBL = sb + OFF_AL + m_l * 1024;
    const int k_ln = lane & 15;
    const int n_l  = wn * 16 + (lane >> 4) * 8;
    const uint32_t bcol = (uint32_t)(((n_l >> 3) ^ (k_ln & 7)) << 4);
    const uint32_t bBH = sb + OFF_BH + k_ln * 128 + bcol;
    const uint32_t bBL = sb + OFF_BL + k_ln * 128 + bcol;

    /* cell role: units cu_u, cu_u+4; batch cu_b */
    const int cu_u = t >> 6, cu_b = t & 63;
    float cst[2] = {0.f, 0.f}, hst[2] = {0.f, 0.f};
    __syncthreads();

    for (int step = 0; step < Ss; step++) {
        const int s = d ? (Ss - 1 - step) : step;
        const int p = step & 1;

        /* stage B hi+lo (128KB linear copy, images pre-swizzled) */
        {
            const float4* srcp = (const float4*)(g_H16 + (size_t)(d * 2 + p) * 2 * 32768);
            float4* dstp = (float4*)(smem + OFF_BH);
#pragma unroll
            for (int i = 0; i < 32; i++) dstp[t + i * 256] = __ldcg(srcp + t + i * 256);
        }
        __syncthreads();

        /* GEMM: m16n16 per warp over K=512 */
        float d0[4] = {0.f,0.f,0.f,0.f}, d1[4] = {0.f,0.f,0.f,0.f};
#pragma unroll 4
        for (int ks = 0; ks < 32; ks++) {
            uint32_t ah0,ah1,ah2,ah3, al0,al1,al2,al3;
            uint32_t bh0,bh1,bh2,bh3, bl0,bl1,bl2,bl3;
            uint32_t asw = (uint32_t)(((2 * ks + kh) ^ me7) << 4);
            LDSM4(ah0,ah1,ah2,ah3, aBH + asw);
            LDSM4(al0,al1,al2,al3, aBL + asw);
            LDSM4T(bh0,bh1,bh2,bh3, bBH + ks * 2048);
            LDSM4T(bl0,bl1,bl2,bl3, bBL + ks * 2048);
            MMA16(d0, ah0,ah1,ah2,ah3, bh0,bh1);
            MMA16(d1, ah0,ah1,ah2,ah3, bh2,bh3);
            MMA16(d0, ah0,ah1,ah2,ah3, bl0,bl1);
            MMA16(d1, ah0,ah1,ah2,ah3, bl2,bl3);
            MMA16(d0, al0,al1,al2,al3, bh0,bh1);
            MMA16(d1, al0,al1,al2,al3, bh2,bh3);
        }
        /* write D to gates smem */
        {
            int g = lane >> 2, tg = lane & 3;
            int r0 = wm * 16 + g, c0 = wn * 16 + tg * 2;
            gate_s[r0 * GP + c0]           = d0[0];
            gate_s[r0 * GP + c0 + 1]       = d0[1];
            gate_s[(r0 + 8) * GP + c0]     = d0[2];
            gate_s[(r0 + 8) * GP + c0 + 1] = d0[3];
            gate_s[r0 * GP + c0 + 8]           = d1[0];
            gate_s[r0 * GP + c0 + 9]           = d1[1];
            gate_s[(r0 + 8) * GP + c0 + 8]     = d1[2];
            gate_s[(r0 + 8) * GP + c0 + 9]     = d1[3];
        }
        __syncthreads();

        /* cell update: 2 cells per thread */
        const int msk = g_xT[s * Bb + cu_b];
        __half* bhi = g_H16 + (size_t)((d * 2 + (1 - p)) * 2) * 32768;
        __half* blo = bhi + 32768;
        const float* xbase = g_xg + ((size_t)(d * Ss + s)) * Gg * Bb;
#pragma unroll
        for (int cc = 0; cc < 2; cc++) {
            int u = cu_u + cc * 4;
            float ig = gate_s[(0 * 8 + u) * GP + cu_b] + __ldg(xbase + (size_t)(0 * Hh + u0 + u) * Bb + cu_b);
            float fg = gate_s[(1 * 8 + u) * GP + cu_b] + __ldg(xbase + (size_t)(1 * Hh + u0 + u) * Bb + cu_b);
            float gg = gate_s[(2 * 8 + u) * GP + cu_b] + __ldg(xbase + (size_t)(2 * Hh + u0 + u) * Bb + cu_b);
            float og = gate_s[(3 * 8 + u) * GP + cu_b] + __ldg(xbase + (size_t)(3 * Hh + u0 + u) * Bb + cu_b);
            float cn = sigm(fg) * cst[cc] + sigm(ig) * tanhf(gg);
            float hn = sigm(og) * tanhf(cn);
            float outv;
            if (msk != 0) { cst[cc] = cn; hst[cc] = hn; outv = hn; }
            else outv = 0.f;
            int ku = u0 + u;
            uint32_t off = (uint32_t)ku * 128 + (((cu_b >> 3) ^ (ku & 7)) << 4) + (cu_b & 7) * 2;
            __half hh = __float2half_rn(hst[cc]);
            *(__half*)((char*)bhi + off) = hh;
            *(__half*)((char*)blo + off) = __float2half_rn(hst[cc] - __half2float(hh));
            g_lstm[((size_t)s * 2 * Hh + d * Hh + ku) * Bb + cu_b] = outv;
        }

        /* inter-block barrier per direction (64 blocks) */
        __threadfence();
        __syncthreads();
        if (t == 0) {
            unsigned tgt = 64u * (unsigned)(step + 1);
            unsigned v = atomicAdd(&g_barc[d], 1u);
            if (v == tgt - 1u) g_barg[d] = tgt;
            else { while (g_barg[d] < tgt) { } }
            __threadfence();
        }
        __syncthreads();
    }
}

/* ---- emissions ---- */
__global__ void emis_kernel(const float* __restrict__ Wlin,
                            const float* __restrict__ blin)
{
    __shared__ float sW[Tt * 2 * Hh];
    int s = blockIdx.x, t = threadIdx.x;
    for (int i = t; i < Tt * 2 * Hh; i += 320) sW[i] = Wlin[i];
    __syncthreads();
    int tag = t >> 6, b = t & 63;
    const float* lp = g_lstm + (size_t)s * 2 * Hh * Bb + b;
    const float* wp = sW + tag * 2 * Hh;
    float acc = 0.f;
#pragma unroll 8
    for (int h = 0; h < 2 * Hh; h++) acc += __ldg(lp + (size_t)h * Bb) * wp[h];
    g_em[((size_t)b * Ss + s) * Tt + tag] = acc + blin[tag];
}

/* ---- CRF ---- */
__global__ void crf_kernel(const int* __restrict__ tags,
                           const int* __restrict__ lengths,
                           const float* __restrict__ trans,
                           const float* __restrict__ start_t,
                           const float* __restrict__ end_t)
{
    int b = blockIdx.x, lane = threadIdx.x;
    const int* tg = tags + (size_t)b * Ss;
    int len = lengths[b];
    float num = 0.f;
    for (int s = lane; s < len; s += 32) {
        int tc = tg[s];
        float e = g_em[((size_t)b * Ss + s) * Tt + tc];
        if (s == 0) num += start_t[tc] + e;
        else        num += trans[tg[s - 1] * Tt + tc] + e;
    }
#pragma unroll
    for (int o = 16; o; o >>= 1) num += __shfl_down_sync(0xffffffffu, num, o);
    num = __shfl_sync(0xffffffffu, num, 0);
    if (lane == 0) num += end_t[tg[len - 1]];
    num = __shfl_sync(0xffffffffu, num, 0);

    int lt = lane < 5 ? lane : 0;
    float trc[5];
#pragma unroll
    for (int i = 0; i < 5; i++) trc[i] = trans[i * Tt + lt];
    float alpha = start_t[lt] + g_em[((size_t)b * Ss) * Tt + lt];
    for (int s = 1; s < len; s++) {
        float av[5];
#pragma unroll
        for (int i = 0; i < 5; i++) av[i] = __shfl_sync(0xffffffffu, alpha, i) + trc[i];
        float mx = av[0];
#pragma unroll
        for (int i = 1; i < 5; i++) mx = fmaxf(mx, av[i]);
        float ssum = 0.f;
#pragma unroll
        for (int i = 0; i < 5; i++) ssum += expf(av[i] - mx);
        float an = mx + logf(ssum) + g_em[((size_t)b * Ss + s) * Tt + lt];
        if (lane < 5) alpha = an;
    }
    float v = (lane < 5) ? alpha + end_t[lane] : -3.0e38f;
    float mx = v;
#pragma unroll
    for (int o = 16; o; o >>= 1) mx = fmaxf(mx, __shfl_xor_sync(0xffffffffu, mx, o));
    float e = (lane < 5) ? expf(v - mx) : 0.f;
#pragma unroll
    for (int o = 16; o; o >>= 1) e += __shfl_xor_sync(0xffffffffu, e, o);
    if (lane == 0) g_scores[b] = mx + logf(e) - num;
}

__global__ void finish_kernel(float* __restrict__ out)
{
    int t = threadIdx.x;
    float v = g_scores[t] + g_scores[t + 32];
#pragma unroll
    for (int o = 16; o; o >>= 1) v += __shfl_down_sync(0xffffffffu, v, o);
    if (t == 0) out[0] = v * (1.f / 64.f);
}

extern "C" void kernel_launch(void* const* d_in, const int* in_sizes, int n_in,
                              void* d_out, int out_size)
{
    const int*   x       = (const int*)d_in[0];
    const int*   tags    = (const int*)d_in[1];
    const int*   lengths = (const int*)d_in[2];
    const float* emb     = (const float*)d_in[3];
    const float* Wih_f   = (const float*)d_in[4];
    const float* Whh_f   = (const float*)d_in[5];
    const float* b_f     = (const float*)d_in[6];
    const float* Wih_b   = (const float*)d_in[7];
    const float* Whh_b   = (const float*)d_in[8];
    const float* b_b     = (const float*)d_in[9];
    const float* Wlin    = (const float*)d_in[10];
    const float* blin    = (const float*)d_in[11];
    const float* trans   = (const float*)d_in[12];
    const float* start_t = (const float*)d_in[13];
    const float* end_t   = (const float*)d_in[14];
    float* out = (float*)d_out;

    cudaFuncSetAttribute(lstm_kernel,
                         cudaFuncAttributeMaxDynamicSharedMemorySize, LSTM_SMEM);

    prep_kernel<<<512, 256>>>(x);
    proj_kernel<<<dim3((Vv + 63) / 64, 4096 / 64), 256>>>(emb, Wih_f, b_f, Wih_b, b_b);
    gather_kernel<<<2 * Ss, 256>>>(x);
    lstm_kernel<<<128, 256, LSTM_SMEM>>>(Whh_f, Whh_b);
    emis_kernel<<<Ss, 320>>>(Wlin, blin);
    crf_kernel<<<Bb, 32>>>(tags, lengths, trans, start_t, end_t);
    finish_kernel<<<1, 32>>>(out);
}

// round 8
// speedup vs baseline: 4.8535x; 1.1603x over previous
#include <cuda_runtime.h>
#include <cuda_fp16.h>
#include <cstdint>
#include <cstddef>

#define Vv 10000
#define Tt 5
#define Ee 256
#define Hh 512
#define Bb 64
#define Ss 512
#define Gg 2048

__device__ float g_P[(size_t)Vv * 4096];
__device__ float g_xg[(size_t)2 * Ss * Gg * Bb];          /* [d][s][g][b] */
__device__ __half g_H16[2 * 2 * 32768];                   /* [d][par][k*64+b swizzled] hi only */
__device__ float g_lstm[(size_t)Ss * 2 * Hh * Bb];        /* [s][h2][b] */
__device__ float g_em[(size_t)Bb * Ss * Tt];
__device__ int   g_xT[Ss * Bb];
__device__ float g_scores[Bb];
__device__ unsigned g_barc[2];
__device__ volatile unsigned g_barg[2];

__device__ __forceinline__ uint32_t smem_u32(const void* p) {
    uint32_t a;
    asm("{ .reg .u64 t; cvta.to.shared.u64 t, %1; cvt.u32.u64 %0, t; }" : "=r"(a) : "l"(p));
    return a;
}
#define LDSM4(r0,r1,r2,r3,ad) asm volatile( \
    "ldmatrix.sync.aligned.m8n8.x4.shared.b16 {%0,%1,%2,%3}, [%4];" \
    : "=r"(r0),"=r"(r1),"=r"(r2),"=r"(r3) : "r"(ad))
#define LDSM4T(r0,r1,r2,r3,ad) asm volatile( \
    "ldmatrix.sync.aligned.m8n8.x4.trans.shared.b16 {%0,%1,%2,%3}, [%4];" \
    : "=r"(r0),"=r"(r1),"=r"(r2),"=r"(r3) : "r"(ad))
#define MMA16(d,a0,a1,a2,a3,b0,b1) asm volatile( \
    "mma.sync.aligned.m16n8k16.row.col.f32.f16.f16.f32 " \
    "{%0,%1,%2,%3}, {%4,%5,%6,%7}, {%8,%9}, {%0,%1,%2,%3};" \
    : "+f"((d)[0]),"+f"((d)[1]),"+f"((d)[2]),"+f"((d)[3]) \
    : "r"(a0),"r"(a1),"r"(a2),"r"(a3),"r"(b0),"r"(b1))

/* ---- prep ---- */
__global__ void prep_kernel(const int* __restrict__ x)
{
    int i = blockIdx.x * blockDim.x + threadIdx.x;       /* 131072 */
    if (i < 65536) ((unsigned*)g_H16)[i] = 0;
    if (i < Ss * Bb) { int s = i >> 6, b = i & 63; g_xT[i] = x[b * Ss + s]; }
    if (i < 2) { g_barc[i] = 0; g_barg[i] = 0; }
}

/* ---- vocab projection: P = emb @ Wih^T + b ---- */
__global__ void __launch_bounds__(256) proj_kernel(
    const float* __restrict__ emb,
    const float* __restrict__ Wf, const float* __restrict__ bf,
    const float* __restrict__ Wb, const float* __restrict__ bb)
{
    __shared__ float sA[32 * 68], sB[32 * 68];
    const int v0 = blockIdx.x * 64, g0 = blockIdx.y * 64;
    const float* W  = (g0 < 2048) ? Wf : Wb;
    const float* bi = (g0 < 2048) ? bf : bb;
    const int gb = (g0 < 2048) ? g0 : g0 - 2048;
    const int tid = threadIdx.x, tx = tid & 15, ty = tid >> 4;
    float acc[4][4];
#pragma unroll
    for (int i = 0; i < 4; i++)
#pragma unroll
        for (int j = 0; j < 4; j++) acc[i][j] = 0.f;
    for (int e0 = 0; e0 < Ee; e0 += 32) {
#pragma unroll
        for (int it = 0; it < 2; it++) {
            int lin = tid + it * 256, row = lin >> 3, q = lin & 7;
            int v = v0 + row; if (v >= Vv) v = Vv - 1;
            float4 a = *(const float4*)&emb[(size_t)v * Ee + e0 + q * 4];
            sA[(q*4+0)*68+row]=a.x; sA[(q*4+1)*68+row]=a.y; sA[(q*4+2)*68+row]=a.z; sA[(q*4+3)*68+row]=a.w;
            float4 w = *(const float4*)&W[(size_t)(gb + row) * Ee + e0 + q * 4];
            sB[(q*4+0)*68+row]=w.x; sB[(q*4+1)*68+row]=w.y; sB[(q*4+2)*68+row]=w.z; sB[(q*4+3)*68+row]=w.w;
        }
        __syncthreads();
#pragma unroll
        for (int e = 0; e < 32; e++) {
            float4 a4 = *(const float4*)&sA[e * 68 + tx * 4];
            float4 b4 = *(const float4*)&sB[e * 68 + ty * 4];
            float av[4] = {a4.x, a4.y, a4.z, a4.w}, bv[4] = {b4.x, b4.y, b4.z, b4.w};
#pragma unroll
            for (int i = 0; i < 4; i++)
#pragma unroll
                for (int j = 0; j < 4; j++) acc[i][j] += av[i] * bv[j];
        }
        __syncthreads();
    }
#pragma unroll
    for (int i = 0; i < 4; i++) {
        int v = v0 + tx * 4 + i;
        if (v < Vv)
#pragma unroll
            for (int j = 0; j < 4; j++)
                g_P[(size_t)v * 4096 + g0 + ty * 4 + j] = acc[i][j] + bi[gb + ty * 4 + j];
    }
}

/* ---- gather+transpose: xg[d][s][g][b] = P[x[b][s]][d*2048+g] ---- */
__global__ void gather_kernel(const int* __restrict__ x)
{
    __shared__ float tile[64 * 68];
    int sb = blockIdx.x, s = sb >> 1, d = sb & 1, t = threadIdx.x;
    int lb = t & 63, lq = t >> 6, wg = t >> 2, wq = t & 3;
    int tok = x[lb * Ss + s];
    const float* src = g_P + (size_t)tok * 4096 + d * 2048;
    float* dst = g_xg + ((size_t)(d * Ss + s)) * Gg * Bb;
    for (int g0 = 0; g0 < Gg; g0 += 64) {
#pragma unroll
        for (int j = 0; j < 4; j++) {
            int col = lq * 16 + j * 4;
            *(float4*)&tile[lb * 68 + col] = __ldg((const float4*)&src[g0 + col]);
        }
        __syncthreads();
        float o[16];
#pragma unroll
        for (int i = 0; i < 16; i++) o[i] = tile[(wq * 16 + i) * 68 + wg];
        float4* ob = (float4*)&dst[(size_t)(g0 + wg) * Bb + wq * 16];
#pragma unroll
        for (int i = 0; i < 4; i++) ob[i] = ((float4*)o)[i];
        __syncthreads();
    }
}

/* ---- persistent BiLSTM via mma.sync f16 (A hi/lo split, B fp16) ----
   128 blocks: d(2) x m(64). Block: 8 hidden units = 32 gate rows x 64 b,
   K = 512. Warp (8): wm = wid&1 (m16), wn = wid>>1 (n16), full K.
   B staged in two 32KB half-K chunks; chunk1 L2 traffic hidden under
   GEMM on chunk0. */
#define OFF_AH 0
#define OFF_AL 32768
#define OFF_B  65536
#define OFF_G  131072
#define GP 66
#define LSTM_SMEM (OFF_G + 32 * GP * 4)

__device__ __forceinline__ float sigm(float x) { return 1.f / (1.f + expf(-x)); }

__global__ void __launch_bounds__(256, 1) lstm_kernel(
    const float* __restrict__ Whh_f, const float* __restrict__ Whh_b)
{
    extern __shared__ char smem[];
    const uint32_t sb = smem_u32(smem);
    float* gate_s = (float*)(smem + OFF_G);
    const int t = threadIdx.x, lane = t & 31, wid = t >> 5;
    const int d = blockIdx.x >> 6, mblk = blockIdx.x & 63;
    const int u0 = mblk * 8;
    const float* Whh = d ? Whh_b : Whh_f;

    /* A split hi/lo into swizzled smem: row r = type*8+u, 1KB rows */
    for (int i = t; i < 32 * 512; i += 256) {
        int r = i >> 9, k = i & 511;
        float w = Whh[(size_t)((r >> 3) * Hh + u0 + (r & 7)) * Hh + k];
        __half hi = __float2half_rn(w);
        __half lo = __float2half_rn(w - __half2float(hi));
        uint32_t off = (uint32_t)r * 1024 + ((((k >> 3) ^ (r & 7))) << 4) + (k & 7) * 2;
        *(__half*)(smem + OFF_AH + off) = hi;
        *(__half*)(smem + OFF_AL + off) = lo;
    }

    /* GEMM role constants */
    const int wm = wid & 1, wn = wid >> 1;
    const int m_l = wm * 16 + (lane & 15);
    const int kh  = lane >> 4;
    const int me7 = m_l & 7;
    const uint32_t aBH = sb + OFF_AH + m_l * 1024;
    const uint32_t aBL = sb + OFF_AL + m_l * 1024;
    const int k_ln = lane & 15;
    const int n_l  = wn * 16 + (lane >> 4) * 8;
    const uint32_t bcol = (uint32_t)(((n_l >> 3) ^ (k_ln & 7)) << 4);
    const uint32_t bBH = sb + OFF_B + k_ln * 128 + bcol;

    /* cell role: units cu_u, cu_u+4; batch cu_b */
    const int cu_u = t >> 6, cu_b = t & 63;
    float cst[2] = {0.f, 0.f}, hst[2] = {0.f, 0.f};
    __syncthreads();

    for (int step = 0; step < Ss; step++) {
        const int s = d ? (Ss - 1 - step) : step;
        const int p = step & 1;

        /* issue all B loads up-front (both 32KB chunks in flight) */
        float4 c0[8], c1[8];
        {
            const float4* srcp = (const float4*)(g_H16 + (size_t)(d * 2 + p) * 32768);
#pragma unroll
            for (int i = 0; i < 8; i++) c0[i] = __ldcg(srcp + t + i * 256);
#pragma unroll
            for (int i = 0; i < 8; i++) c1[i] = __ldcg(srcp + 2048 + t + i * 256);
        }
        float4* dstp = (float4*)(smem + OFF_B);
#pragma unroll
        for (int i = 0; i < 8; i++) dstp[t + i * 256] = c0[i];
        __syncthreads();

        float d0[4] = {0.f,0.f,0.f,0.f}, d1[4] = {0.f,0.f,0.f,0.f};
        /* GEMM chunk0: k = 0..255 (chunk1 L2 traffic hidden underneath) */
#pragma unroll 4
        for (int ks = 0; ks < 16; ks++) {
            uint32_t ah0,ah1,ah2,ah3, al0,al1,al2,al3, bh0,bh1,bh2,bh3;
            uint32_t asw = (uint32_t)(((2 * ks + kh) ^ me7) << 4);
            LDSM4(ah0,ah1,ah2,ah3, aBH + asw);
            LDSM4(al0,al1,al2,al3, aBL + asw);
            LDSM4T(bh0,bh1,bh2,bh3, bBH + ks * 2048);
            MMA16(d0, ah0,ah1,ah2,ah3, bh0,bh1);
            MMA16(d1, ah0,ah1,ah2,ah3, bh2,bh3);
            MMA16(d0, al0,al1,al2,al3, bh0,bh1);
            MMA16(d1, al0,al1,al2,al3, bh2,bh3);
        }
        /* stage chunk1, then GEMM k = 256..511 */
#pragma unroll
        for (int i = 0; i < 8; i++) dstp[2048 + t + i * 256] = c1[i];
        __syncthreads();
#pragma unroll 4
        for (int ks = 16; ks < 32; ks++) {
            uint32_t ah0,ah1,ah2,ah3, al0,al1,al2,al3, bh0,bh1,bh2,bh3;
            uint32_t asw = (uint32_t)(((2 * ks + kh) ^ me7) << 4);
            LDSM4(ah0,ah1,ah2,ah3, aBH + asw);
            LDSM4(al0,al1,al2,al3, aBL + asw);
            LDSM4T(bh0,bh1,bh2,bh3, bBH + ks * 2048);
            MMA16(d0, ah0,ah1,ah2,ah3, bh0,bh1);
            MMA16(d1, ah0,ah1,ah2,ah3, bh2,bh3);
            MMA16(d0, al0,al1,al2,al3, bh0,bh1);
            MMA16(d1, al0,al1,al2,al3, bh2,bh3);
        }
        /* write D to gates smem */
        {
            int g = lane >> 2, tg = lane & 3;
            int r0 = wm * 16 + g, c0i = wn * 16 + tg * 2;
            gate_s[r0 * GP + c0i]           = d0[0];
            gate_s[r0 * GP + c0i + 1]       = d0[1];
            gate_s[(r0 + 8) * GP + c0i]     = d0[2];
            gate_s[(r0 + 8) * GP + c0i + 1] = d0[3];
            gate_s[r0 * GP + c0i + 8]           = d1[0];
            gate_s[r0 * GP + c0i + 9]           = d1[1];
            gate_s[(r0 + 8) * GP + c0i + 8]     = d1[2];
            gate_s[(r0 + 8) * GP + c0i + 9]     = d1[3];
        }
        __syncthreads();

        /* cell update: 2 cells per thread */
        const int msk = g_xT[s * Bb + cu_b];
        __half* bhi = g_H16 + (size_t)(d * 2 + (1 - p)) * 32768;
        const float* xbase = g_xg + ((size_t)(d * Ss + s)) * Gg * Bb;
#pragma unroll
        for (int cc = 0; cc < 2; cc++) {
            int u = cu_u + cc * 4;
            float ig = gate_s[(0 * 8 + u) * GP + cu_b] + __ldg(xbase + (size_t)(0 * Hh + u0 + u) * Bb + cu_b);
            float fg = gate_s[(1 * 8 + u) * GP + cu_b] + __ldg(xbase + (size_t)(1 * Hh + u0 + u) * Bb + cu_b);
            float gg = gate_s[(2 * 8 + u) * GP + cu_b] + __ldg(xbase + (size_t)(2 * Hh + u0 + u) * Bb + cu_b);
            float og = gate_s[(3 * 8 + u) * GP + cu_b] + __ldg(xbase + (size_t)(3 * Hh + u0 + u) * Bb + cu_b);
            float cn = sigm(fg) * cst[cc] + sigm(ig) * tanhf(gg);
            float hn = sigm(og) * tanhf(cn);
            float outv;
            if (msk != 0) { cst[cc] = cn; hst[cc] = hn; outv = hn; }
            else outv = 0.f;
            int ku = u0 + u;
            uint32_t off = (uint32_t)ku * 128 + (((cu_b >> 3) ^ (ku & 7)) << 4) + (cu_b & 7) * 2;
            *(__half*)((char*)bhi + off) = __float2half_rn(hst[cc]);
            g_lstm[((size_t)s * 2 * Hh + d * Hh + ku) * Bb + cu_b] = outv;
        }

        /* inter-block barrier per direction (64 blocks) */
        __threadfence();
        __syncthreads();
        if (t == 0) {
            unsigned tgt = 64u * (unsigned)(step + 1);
            unsigned v = atomicAdd(&g_barc[d], 1u);
            if (v == tgt - 1u) g_barg[d] = tgt;
            else { while (g_barg[d] < tgt) { } }
            __threadfence();
        }
        __syncthreads();
    }
}

/* ---- emissions ---- */
__global__ void emis_kernel(const float* __restrict__ Wlin,
                            const float* __restrict__ blin)
{
    __shared__ float sW[Tt * 2 * Hh];
    int s = blockIdx.x, t = threadIdx.x;
    for (int i = t; i < Tt * 2 * Hh; i += 320) sW[i] = Wlin[i];
    __syncthreads();
    int tag = t >> 6, b = t & 63;
    const float* lp = g_lstm + (size_t)s * 2 * Hh * Bb + b;
    const float* wp = sW + tag * 2 * Hh;
    float acc = 0.f;
#pragma unroll 8
    for (int h = 0; h < 2 * Hh; h++) acc += __ldg(lp + (size_t)h * Bb) * wp[h];
    g_em[((size_t)b * Ss + s) * Tt + tag] = acc + blin[tag];
}

/* ---- CRF ---- */
__global__ void crf_kernel(const int* __restrict__ tags,
                           const int* __restrict__ lengths,
                           const float* __restrict__ trans,
                           const float* __restrict__ start_t,
                           const float* __restrict__ end_t)
{
    int b = blockIdx.x, lane = threadIdx.x;
    const int* tg = tags + (size_t)b * Ss;
    int len = lengths[b];
    float num = 0.f;
    for (int s = lane; s < len; s += 32) {
        int tc = tg[s];
        float e = g_em[((size_t)b * Ss + s) * Tt + tc];
        if (s == 0) num += start_t[tc] + e;
        else        num += trans[tg[s - 1] * Tt + tc] + e;
    }
#pragma unroll
    for (int o = 16; o; o >>= 1) num += __shfl_down_sync(0xffffffffu, num, o);
    num = __shfl_sync(0xffffffffu, num, 0);
    if (lane == 0) num += end_t[tg[len - 1]];
    num = __shfl_sync(0xffffffffu, num, 0);

    int lt = lane < 5 ? lane : 0;
    float trc[5];
#pragma unroll
    for (int i = 0; i < 5; i++) trc[i] = trans[i * Tt + lt];
    float alpha = start_t[lt] + g_em[((size_t)b * Ss) * Tt + lt];
    for (int s = 1; s < len; s++) {
        float av[5];
#pragma unroll
        for (int i = 0; i < 5; i++) av[i] = __shfl_sync(0xffffffffu, alpha, i) + trc[i];
        float mx = av[0];
#pragma unroll
        for (int i = 1; i < 5; i++) mx = fmaxf(mx, av[i]);
        float ssum = 0.f;
#pragma unroll
        for (int i = 0; i < 5; i++) ssum += expf(av[i] - mx);
        float an = mx + logf(ssum) + g_em[((size_t)b * Ss + s) * Tt + lt];
        if (lane < 5) alpha = an;
    }
    float v = (lane < 5) ? alpha + end_t[lane] : -3.0e38f;
    float mx = v;
#pragma unroll
    for (int o = 16; o; o >>= 1) mx = fmaxf(mx, __shfl_xor_sync(0xffffffffu, mx, o));
    float e = (lane < 5) ? expf(v - mx) : 0.f;
#pragma unroll
    for (int o = 16; o; o >>= 1) e += __shfl_xor_sync(0xffffffffu, e, o);
    if (lane == 0) g_scores[b] = mx + logf(e) - num;
}

__global__ void finish_kernel(float* __restrict__ out)
{
    int t = threadIdx.x;
    float v = g_scores[t] + g_scores[t + 32];
#pragma unroll
    for (int o = 16; o; o >>= 1) v += __shfl_down_sync(0xffffffffu, v, o);
    if (t == 0) out[0] = v * (1.f / 64.f);
}

extern "C" void kernel_launch(void* const* d_in, const int* in_sizes, int n_in,
                              void* d_out, int out_size)
{
    const int*   x       = (const int*)d_in[0];
    const int*   tags    = (const int*)d_in[1];
    const int*   lengths = (const int*)d_in[2];
    const float* emb     = (const float*)d_in[3];
    const float* Wih_f   = (const float*)d_in[4];
    const float* Whh_f   = (const float*)d_in[5];
    const float* b_f     = (const float*)d_in[6];
    const float* Wih_b   = (const float*)d_in[7];
    const float* Whh_b   = (const float*)d_in[8];
    const float* b_b     = (const float*)d_in[9];
    const float* Wlin    = (const float*)d_in[10];
    const float* blin    = (const float*)d_in[11];
    const float* trans   = (const float*)d_in[12];
    const float* start_t = (const float*)d_in[13];
    const float* end_t   = (const float*)d_in[14];
    float* out = (float*)d_out;

    cudaFuncSetAttribute(lstm_kernel,
                         cudaFuncAttributeMaxDynamicSharedMemorySize, LSTM_SMEM);

    prep_kernel<<<512, 256>>>(x);
    proj_kernel<<<dim3((Vv + 63) / 64, 4096 / 64), 256>>>(emb, Wih_f, b_f, Wih_b, b_b);
    gather_kernel<<<2 * Ss, 256>>>(x);
    lstm_kernel<<<128, 256, LSTM_SMEM>>>(Whh_f, Whh_b);
    emis_kernel<<<Ss, 320>>>(Wlin, blin);
    crf_kernel<<<Bb, 32>>>(tags, lengths, trans, start_t, end_t);
    finish_kernel<<<1, 32>>>(out);
}